// round 1
// baseline (speedup 1.0000x reference)
#include <cuda_runtime.h>

// Problem constants (fixed shapes from setup_inputs)
#define BN 4
#define BC 64
#define BH 256
#define BW 448
#define BHW (BH * BW)            // 114688
#define ACC_FLOATS (BN * BHW * BC)   // 29,360,128  (NHWC accumulation)
#define NORM_FLOATS (BN * BHW)       // 458,752
#define TOTAL_FLOATS (ACC_FLOATS + NORM_FLOATS)
#define TOTAL_F4 (TOTAL_FLOATS / 4)  // 7,454,720

// Scratch: NHWC accumulator followed by norm plane. Static __device__ global
// (module-load allocation — allowed; no runtime allocs anywhere).
__device__ float4 g_scratch[TOTAL_F4];

// ---------------------------------------------------------------------------
// Kernel 1: zero the scratch
// ---------------------------------------------------------------------------
__global__ void kzero(void) {
    int i = blockIdx.x * blockDim.x + threadIdx.x;
    if (i < TOTAL_F4) {
        g_scratch[i] = make_float4(0.f, 0.f, 0.f, 0.f);
    }
}

// ---------------------------------------------------------------------------
// Kernel 2: scatter (softsplat) into NHWC accumulator with red.global.add.v4
// block = (32 x-lanes, 16 channel-groups of 4), grid = (W/32, H, N)
// ---------------------------------------------------------------------------
__device__ __forceinline__ void red_add_v4(float* p, float a, float b, float c, float d) {
    asm volatile("red.global.add.v4.f32 [%0], {%1, %2, %3, %4};"
                 :: "l"(p), "f"(a), "f"(b), "f"(c), "f"(d)
                 : "memory");
}

__global__ __launch_bounds__(512)
void ksplat(const float* __restrict__ inp,
            const float* __restrict__ flow,
            const float* __restrict__ metric) {
    float* acc  = reinterpret_cast<float*>(g_scratch);          // [N][H][W][C]
    float* norm = acc + ACC_FLOATS;                             // [N][H][W]

    const int n = blockIdx.z;
    const int y = blockIdx.y;
    const int x = blockIdx.x * 32 + threadIdx.x;
    const int c = threadIdx.y * 4;

    const int pix = (n * BH + y) * BW + x;

    const float fx = flow[(n * 2 + 0) * BHW + y * BW + x];
    const float fy = flow[(n * 2 + 1) * BHW + y * BW + x];
    const float m  = __expf(metric[pix]);

    const float* ib = inp + ((size_t)(n * BC + c)) * BHW + y * BW + x;
    const float v0 = ib[0 * BHW] * m;
    const float v1 = ib[1 * BHW] * m;
    const float v2 = ib[2 * BHW] * m;
    const float v3 = ib[3 * BHW] * m;

    const float xx = (float)x + fx;
    const float yy = (float)y + fy;
    const float fx0 = floorf(xx);
    const float fy0 = floorf(yy);
    const int ix0 = (int)fx0;
    const int iy0 = (int)fy0;
    const float tx = xx - fx0;
    const float ty = yy - fy0;

    const float w00 = (1.f - tx) * (1.f - ty);
    const float w10 = tx * (1.f - ty);
    const float w01 = (1.f - tx) * ty;
    const float w11 = tx * ty;

    const bool xv0 = (ix0 >= 0) && (ix0 < BW);
    const bool xv1 = (ix0 + 1 >= 0) && (ix0 + 1 < BW);
    const bool yv0 = (iy0 >= 0) && (iy0 < BH);
    const bool yv1 = (iy0 + 1 >= 0) && (iy0 + 1 < BH);

    const int rowbase = n * BHW;
    const bool do_norm = (threadIdx.y == 0);

    #define SPLAT(IX, IY, WGT)                                            \
        do {                                                              \
            int d = rowbase + (IY) * BW + (IX);                           \
            red_add_v4(acc + (size_t)d * BC + c,                          \
                       (WGT) * v0, (WGT) * v1, (WGT) * v2, (WGT) * v3);   \
            if (do_norm) atomicAdd(norm + d, (WGT) * m);                  \
        } while (0)

    if (xv0 && yv0) SPLAT(ix0,     iy0,     w00);
    if (xv1 && yv0) SPLAT(ix0 + 1, iy0,     w10);
    if (xv0 && yv1) SPLAT(ix0,     iy0 + 1, w01);
    if (xv1 && yv1) SPLAT(ix0 + 1, iy0 + 1, w11);
    #undef SPLAT
}

// ---------------------------------------------------------------------------
// Kernel 3: normalize + NHWC -> NCHW transpose via smem tile
// block = 256 threads handling a 32x(x) by 64(c) tile for fixed (n, y)
// ---------------------------------------------------------------------------
__global__ __launch_bounds__(256)
void knorm(float* __restrict__ out) {
    const float* acc  = reinterpret_cast<const float*>(g_scratch);
    const float* norm = acc + ACC_FLOATS;

    __shared__ float sm[64][33];
    __shared__ float sinv[32];

    const int n  = blockIdx.z;
    const int y  = blockIdx.y;
    const int x0 = blockIdx.x * 32;
    const int tid = threadIdx.x;

    const float* accbase = acc + (size_t)((n * BH + y) * BW + x0) * BC;

    #pragma unroll
    for (int i = 0; i < 2; i++) {
        int idx = tid + i * 256;      // 512 float4s: 32 px * 16 f4
        int px = idx >> 4;
        int f4 = idx & 15;
        float4 v = *reinterpret_cast<const float4*>(accbase + px * BC + f4 * 4);
        int c = f4 * 4;
        sm[c + 0][px] = v.x;
        sm[c + 1][px] = v.y;
        sm[c + 2][px] = v.z;
        sm[c + 3][px] = v.w;
    }
    if (tid < 32) {
        float nv = norm[(n * BH + y) * BW + x0 + tid];
        sinv[tid] = (nv == 0.f) ? 1.f : (1.f / nv);
    }
    __syncthreads();

    const int warp = tid >> 5;
    const int lane = tid & 31;
    const float inv = sinv[lane];

    #pragma unroll
    for (int r = 0; r < 8; r++) {
        int c = warp * 8 + r;
        out[((size_t)(n * BC + c) * BH + y) * BW + x0 + lane] = sm[c][lane] * inv;
    }
}

// ---------------------------------------------------------------------------
extern "C" void kernel_launch(void* const* d_in, const int* in_sizes, int n_in,
                              void* d_out, int out_size) {
    const float* inp    = (const float*)d_in[0];  // (4,64,256,448)
    const float* flow   = (const float*)d_in[1];  // (4,2,256,448)
    const float* metric = (const float*)d_in[2];  // (4,1,256,448)
    float* out = (float*)d_out;                   // (4,64,256,448)

    (void)in_sizes; (void)n_in; (void)out_size;

    kzero<<<(TOTAL_F4 + 255) / 256, 256>>>();

    dim3 gsplat(BW / 32, BH, BN);
    dim3 bsplat(32, 16, 1);
    ksplat<<<gsplat, bsplat>>>(inp, flow, metric);

    dim3 gnorm(BW / 32, BH, BN);
    knorm<<<gnorm, 256>>>(out);
}

// round 2
// speedup vs baseline: 1.0195x; 1.0195x over previous
#include <cuda_runtime.h>

// Fixed shapes from setup_inputs
#define BN 4
#define BC 64
#define BH 256
#define BW 448
#define BHW (BH * BW)                 // 114688
#define ACC_FLOATS (BN * BHW * BC)    // 29,360,128 (NHWC accumulation)
#define NORM_FLOATS (BN * BHW)        // 458,752
#define TOTAL_F4 ((ACC_FLOATS + NORM_FLOATS) / 4)

#define ACC_F4_IMG (BHW * BC / 4)     // 1,835,008
#define NORM_F4_IMG (BHW / 4)         // 28,672
#define ZERO_F4_IMG (ACC_F4_IMG + NORM_F4_IMG)

// Static scratch (module-load allocation — allowed). Layout:
//   [0 .. ACC_FLOATS)                : acc  [N][H][W][C]
//   [ACC_FLOATS .. +NORM_FLOATS)     : norm [N][H][W]
__device__ float4 g_scratch[TOTAL_F4];

// ---------------------------------------------------------------------------
// Kernel 1: zero one image's scratch slice
// ---------------------------------------------------------------------------
__global__ __launch_bounds__(256)
void kzero(int n) {
    int i = blockIdx.x * blockDim.x + threadIdx.x;
    float4 z = make_float4(0.f, 0.f, 0.f, 0.f);
    if (i < ACC_F4_IMG) {
        g_scratch[(size_t)n * ACC_F4_IMG + i] = z;
    } else if (i < ZERO_F4_IMG) {
        g_scratch[ACC_FLOATS / 4 + (size_t)n * NORM_F4_IMG + (i - ACC_F4_IMG)] = z;
    }
}

// ---------------------------------------------------------------------------
// Kernel 2: scatter one image into NHWC accumulator (red.global.add.v4)
// block = (32 x-lanes, 8 channel-groups of 8), grid = (W/32, H)
// ---------------------------------------------------------------------------
__device__ __forceinline__ void red_add_v4(float* p, float a, float b, float c, float d) {
    asm volatile("red.global.add.v4.f32 [%0], {%1, %2, %3, %4};"
                 :: "l"(p), "f"(a), "f"(b), "f"(c), "f"(d)
                 : "memory");
}

__global__ __launch_bounds__(256)
void ksplat(const float* __restrict__ inp,
            const float* __restrict__ flow,
            const float* __restrict__ metric,
            int n) {
    float* acc  = reinterpret_cast<float*>(g_scratch);   // [N][H][W][C]
    float* norm = acc + ACC_FLOATS;                      // [N][H][W]

    const int y = blockIdx.y;
    const int x = blockIdx.x * 32 + threadIdx.x;
    const int c = threadIdx.y * 8;

    const int pix = (n * BH + y) * BW + x;

    const float fx = __ldg(flow + (n * 2 + 0) * BHW + y * BW + x);
    const float fy = __ldg(flow + (n * 2 + 1) * BHW + y * BW + x);
    const float m  = __expf(__ldg(metric + pix));

    const float* ib = inp + ((size_t)(n * BC + c)) * BHW + y * BW + x;
    float v[8];
    #pragma unroll
    for (int k = 0; k < 8; k++) v[k] = __ldg(ib + (size_t)k * BHW) * m;

    const float xx = (float)x + fx;
    const float yy = (float)y + fy;
    const float fx0 = floorf(xx);
    const float fy0 = floorf(yy);
    const int ix0 = (int)fx0;
    const int iy0 = (int)fy0;
    const float tx = xx - fx0;
    const float ty = yy - fy0;

    const float w00 = (1.f - tx) * (1.f - ty);
    const float w10 = tx * (1.f - ty);
    const float w01 = (1.f - tx) * ty;
    const float w11 = tx * ty;

    const bool xv0 = (ix0 >= 0) && (ix0 < BW);
    const bool xv1 = (ix0 + 1 >= 0) && (ix0 + 1 < BW);
    const bool yv0 = (iy0 >= 0) && (iy0 < BH);
    const bool yv1 = (iy0 + 1 >= 0) && (iy0 + 1 < BH);

    const int rowbase = n * BHW;
    const bool do_norm = (threadIdx.y == 0);

    #define SPLAT(IX, IY, WGT)                                              \
        do {                                                                \
            int d = rowbase + (IY) * BW + (IX);                             \
            float* p = acc + (size_t)d * BC + c;                            \
            red_add_v4(p,     (WGT) * v[0], (WGT) * v[1],                   \
                              (WGT) * v[2], (WGT) * v[3]);                  \
            red_add_v4(p + 4, (WGT) * v[4], (WGT) * v[5],                   \
                              (WGT) * v[6], (WGT) * v[7]);                  \
            if (do_norm) atomicAdd(norm + d, (WGT) * m);                    \
        } while (0)

    if (xv0 && yv0) SPLAT(ix0,     iy0,     w00);
    if (xv1 && yv0) SPLAT(ix0 + 1, iy0,     w10);
    if (xv0 && yv1) SPLAT(ix0,     iy0 + 1, w01);
    if (xv1 && yv1) SPLAT(ix0 + 1, iy0 + 1, w11);
    #undef SPLAT
}

// ---------------------------------------------------------------------------
// Kernel 3: normalize + NHWC -> NCHW transpose for one image
// block = 256 threads, 32(x) x 64(c) tile at fixed (n, y)
// ---------------------------------------------------------------------------
__global__ __launch_bounds__(256)
void knorm(float* __restrict__ out, int n) {
    const float* acc  = reinterpret_cast<const float*>(g_scratch);
    const float* norm = acc + ACC_FLOATS;

    __shared__ float sm[64][33];
    __shared__ float sinv[32];

    const int y  = blockIdx.y;
    const int x0 = blockIdx.x * 32;
    const int tid = threadIdx.x;

    const float* accbase = acc + (size_t)((n * BH + y) * BW + x0) * BC;

    #pragma unroll
    for (int i = 0; i < 2; i++) {
        int idx = tid + i * 256;      // 512 float4s: 32 px * 16 f4
        int px = idx >> 4;
        int f4 = idx & 15;
        float4 v = *reinterpret_cast<const float4*>(accbase + px * BC + f4 * 4);
        int c = f4 * 4;
        sm[c + 0][px] = v.x;
        sm[c + 1][px] = v.y;
        sm[c + 2][px] = v.z;
        sm[c + 3][px] = v.w;
    }
    if (tid < 32) {
        float nv = norm[(n * BH + y) * BW + x0 + tid];
        sinv[tid] = (nv == 0.f) ? 1.f : (1.f / nv);
    }
    __syncthreads();

    const int warp = tid >> 5;
    const int lane = tid & 31;
    const float inv = sinv[lane];

    #pragma unroll
    for (int r = 0; r < 8; r++) {
        int c = warp * 8 + r;
        out[((size_t)(n * BC + c) * BH + y) * BW + x0 + lane] = sm[c][lane] * inv;
    }
}

// ---------------------------------------------------------------------------
extern "C" void kernel_launch(void* const* d_in, const int* in_sizes, int n_in,
                              void* d_out, int out_size) {
    const float* inp    = (const float*)d_in[0];  // (4,64,256,448)
    const float* flow   = (const float*)d_in[1];  // (4,2,256,448)
    const float* metric = (const float*)d_in[2];  // (4,1,256,448)
    float* out = (float*)d_out;                   // (4,64,256,448)

    (void)in_sizes; (void)n_in; (void)out_size;

    const int zgrid = (ZERO_F4_IMG + 255) / 256;
    dim3 gsplat(BW / 32, BH);
    dim3 bsplat(32, 8, 1);
    dim3 gnorm(BW / 32, BH);

    for (int n = 0; n < BN; n++) {
        kzero<<<zgrid, 256>>>(n);
        ksplat<<<gsplat, bsplat>>>(inp, flow, metric, n);
        knorm<<<gnorm, 256>>>(out, n);
    }
}